// round 10
// baseline (speedup 1.0000x reference)
#include <cuda_runtime.h>

#define N_NODES 50000
#define N_EDGES 800000
#define F_IN    500
#define H       96
#define NCHUNK  ((N_NODES + 1023) / 1024)   // 49

typedef unsigned long long ull;

// ---------------- device scratch (no allocations allowed) ----------------
__device__ float d_norm_out[N_NODES];
__device__ float d_norm_out2[2 * N_NODES];  // duplicated for merged layer-2 GEMM
__device__ float d_norm_in[N_NODES];
__device__ int   d_deg_out[N_NODES];
__device__ int   d_deg_in[N_NODES];
__device__ int   d_row_ptr[N_NODES + 1];
__device__ int   d_cursor[N_NODES];
__device__ int   d_chunksum[NCHUNK];
__device__ int   d_chunkoff[NCHUNK];
__device__ int   d_col[N_EDGES];            // src ids grouped by dst
__device__ int   d_col2[N_EDGES];           // perm[src] grouped by dst (view 2)
__device__ float d_colw[N_EDGES];           // norm_out[src] per edge
__device__ float d_Y[N_NODES * H];          // x @ W1 (shared by both views)
__device__ float d_t2[2 * N_NODES * H];     // both views stacked
__device__ float d_h2[2 * N_NODES * H];
__device__ float d_wvec[H];                 // Wm @ ones
__device__ float d_bsum;                    // sum(bm)

// ---------------- f32x2 packed FMA helpers ----------------
__device__ __forceinline__ ull ffma2(ull a, ull b, ull c) {
    ull d;
    asm("fma.rn.f32x2 %0, %1, %2, %3;" : "=l"(d) : "l"(a), "l"(b), "l"(c));
    return d;
}
__device__ __forceinline__ ull pack2(float lo, float hi) {
    ull d;
    asm("mov.b64 %0, {%1, %2};" : "=l"(d) : "f"(lo), "f"(hi));
    return d;
}
__device__ __forceinline__ float2 unpack2(ull v) {
    float2 f;
    asm("mov.b64 {%0, %1}, %2;" : "=f"(f.x), "=f"(f.y) : "l"(v));
    return f;
}

// ---------------- degree / norm ----------------
__global__ void k_zero_deg() {
    int i = blockIdx.x * blockDim.x + threadIdx.x;
    if (i < N_NODES) { d_deg_out[i] = 0; d_deg_in[i] = 0; }
}

__global__ void k_count(const int* __restrict__ src, const int* __restrict__ dst) {
    int e = blockIdx.x * blockDim.x + threadIdx.x;
    if (e < N_EDGES) {
        atomicAdd(&d_deg_out[src[e]], 1);
        atomicAdd(&d_deg_in[dst[e]], 1);
    }
}

__global__ void k_norm() {
    int i = blockIdx.x * blockDim.x + threadIdx.x;
    if (i < N_NODES) {
        int dor = d_deg_out[i]; if (dor < 1) dor = 1;
        int din = d_deg_in[i];  if (din < 1) din = 1;
        float no = rsqrtf((float)dor);
        d_norm_out[i] = no;
        d_norm_out2[i] = no;
        d_norm_out2[i + N_NODES] = no;
        d_norm_in[i]  = rsqrtf((float)din);
    }
}

// ---------------- parallel exclusive scan (3 phases, proven ~5us) ----------------
__global__ void k_scan1() {
    int tid = threadIdx.x;
    int i = blockIdx.x * 1024 + tid;
    int v = (i < N_NODES) ? d_deg_in[i] : 0;
    int lane = tid & 31, wid = tid >> 5;

    int inc = v;
    #pragma unroll
    for (int off = 1; off < 32; off <<= 1) {
        int t = __shfl_up_sync(0xffffffffu, inc, off);
        if (lane >= off) inc += t;
    }
    __shared__ int wsum[32];
    if (lane == 31) wsum[wid] = inc;
    __syncthreads();
    if (wid == 0) {
        int w = wsum[lane];
        #pragma unroll
        for (int off = 1; off < 32; off <<= 1) {
            int t = __shfl_up_sync(0xffffffffu, w, off);
            if (lane >= off) w += t;
        }
        wsum[lane] = w;
    }
    __syncthreads();
    int base = wid ? wsum[wid - 1] : 0;
    if (i < N_NODES) d_row_ptr[i] = base + inc - v;
    if (tid == 1023) d_chunksum[blockIdx.x] = base + inc;
}

__global__ void k_scan2() {
    __shared__ int s[64];
    int tid = threadIdx.x;
    int v = (tid < NCHUNK) ? d_chunksum[tid] : 0;
    s[tid] = v;
    __syncthreads();
    #pragma unroll
    for (int off = 1; off < 64; off <<= 1) {
        int t = (tid >= off) ? s[tid - off] : 0;
        __syncthreads();
        s[tid] += t;
        __syncthreads();
    }
    if (tid < NCHUNK) d_chunkoff[tid] = s[tid] - v;
}

__global__ void k_scan3() {
    int i = blockIdx.x * blockDim.x + threadIdx.x;
    if (i < N_NODES) {
        int r = d_row_ptr[i] + d_chunkoff[i >> 10];
        d_row_ptr[i] = r;
        d_cursor[i] = r;
    }
    if (i == 0) d_row_ptr[N_NODES] = N_EDGES;
}

// ---------------- CSR build with folded edge data ----------------
__global__ void k_build_csr(const int* __restrict__ src, const int* __restrict__ dst,
                            const int* __restrict__ perm) {
    int e = blockIdx.x * blockDim.x + threadIdx.x;
    if (e < N_EDGES) {
        int d = dst[e];
        int s = src[e];
        int pos = atomicAdd(&d_cursor[d], 1);
        d_col[pos]  = s;
        d_col2[pos] = perm[s];
        d_colw[pos] = d_norm_out[s];
    }
}

// ---------------- fold Wm into a vector ----------------
__global__ void k_fold(const float* __restrict__ Wm, const float* __restrict__ bm) {
    int j = threadIdx.x;
    if (j < H) {
        float s = 0.f;
        #pragma unroll 4
        for (int k = 0; k < H; k++) s += Wm[j * H + k];
        d_wvec[j] = s;
    }
    if (j == H) {
        float s = 0.f;
        for (int k = 0; k < H; k++) s += bm[k];
        d_bsum = s;
    }
}

// ---------------- SGEMM: C[M,96] = (rowscale .* A[M,K]) @ B[K,96] ----------------
// BM=64, BN=96, BK=16, 256 threads, 4x6 micro-tile executed as 2x6 f32x2 FFMA2.
// sA padded to 68 floats/row: every sA[kk][ty*4] is 16B-aligned -> LDS.128.
// sB stored duplicated {v,v} -> b operand is a single LDS.64 per column.
__global__ void __launch_bounds__(256) sgemm_n96(
        const float* __restrict__ A, int K,
        const float* __restrict__ B,
        const float* __restrict__ rowscale,
        float* __restrict__ C, int M) {
    const int BM = 64, BN = 96, BK = 16;
    __shared__ __align__(16) float sA[BK][BM + 4];   // 68 floats/row = 272B (16B mult)
    __shared__ __align__(16) float2 sB2[BK][BN];     // duplicated pairs

    int tid = threadIdx.x;
    int tx = tid & 15;          // 16 col groups (6 cols each)
    int ty = tid >> 4;          // 16 row groups (4 rows each)
    int bm0 = blockIdx.x * BM;

    ull acc2[2][6];             // row-pairs (2p,2p+1) x 6 cols
    #pragma unroll
    for (int p = 0; p < 2; p++)
        #pragma unroll
        for (int j = 0; j < 6; j++) acc2[p][j] = 0ull;

    int KF = K & ~(BK - 1);

    for (int k0 = 0; k0 < KF; k0 += BK) {
        // A tile: transposed, optional row scale
        #pragma unroll
        for (int i = 0; i < (BM * BK) / 256; i++) {
            int idx = tid + i * 256;
            int r = idx / BK, c = idx % BK;
            int gr = bm0 + r;
            float v = 0.f;
            if (gr < M) {
                v = A[gr * K + k0 + c];
                if (rowscale) v *= rowscale[gr];
            }
            sA[c][r] = v;
        }
        // B tile: duplicated store
        #pragma unroll
        for (int i = 0; i < (BK * BN) / 256; i++) {
            int idx = tid + i * 256;
            int r = idx / BN, c = idx % BN;
            float v = B[(k0 + r) * BN + c];
            sB2[r][c] = make_float2(v, v);
        }
        __syncthreads();

        #pragma unroll
        for (int kk = 0; kk < BK; kk++) {
            float4 va = *(const float4*)&sA[kk][ty * 4];
            ull a01 = pack2(va.x, va.y);
            ull a23 = pack2(va.z, va.w);
            const ull* bp = (const ull*)&sB2[kk][tx * 6];
            #pragma unroll
            for (int j = 0; j < 6; j++) {
                ull b = bp[j];
                acc2[0][j] = ffma2(a01, b, acc2[0][j]);
                acc2[1][j] = ffma2(a23, b, acc2[1][j]);
            }
        }
        __syncthreads();
    }

    // K tail (K=500 -> 4 cols), guarded + zero-padded
    if (KF < K) {
        #pragma unroll
        for (int i = 0; i < (BM * BK) / 256; i++) {
            int idx = tid + i * 256;
            int r = idx / BK, c = idx % BK;
            int gr = bm0 + r, gc = KF + c;
            float v = 0.f;
            if (gr < M && gc < K) {
                v = A[gr * K + gc];
                if (rowscale) v *= rowscale[gr];
            }
            sA[c][r] = v;
        }
        #pragma unroll
        for (int i = 0; i < (BK * BN) / 256; i++) {
            int idx = tid + i * 256;
            int r = idx / BN, c = idx % BN;
            int gk = KF + r;
            float v = (gk < K) ? B[gk * BN + c] : 0.f;
            sB2[r][c] = make_float2(v, v);
        }
        __syncthreads();
        #pragma unroll
        for (int kk = 0; kk < BK; kk++) {
            float4 va = *(const float4*)&sA[kk][ty * 4];
            ull a01 = pack2(va.x, va.y);
            ull a23 = pack2(va.z, va.w);
            const ull* bp = (const ull*)&sB2[kk][tx * 6];
            #pragma unroll
            for (int j = 0; j < 6; j++) {
                ull b = bp[j];
                acc2[0][j] = ffma2(a01, b, acc2[0][j]);
                acc2[1][j] = ffma2(a23, b, acc2[1][j]);
            }
        }
        __syncthreads();
    }

    #pragma unroll
    for (int p = 0; p < 2; p++) {
        #pragma unroll
        for (int l = 0; l < 2; l++) {
            int gr = bm0 + ty * 4 + p * 2 + l;
            if (gr < M) {
                #pragma unroll
                for (int j = 0; j < 6; j++) {
                    float2 f = unpack2(acc2[p][j]);
                    C[gr * 96 + tx * 6 + j] = l ? f.y : f.x;
                }
            }
        }
    }
}

// ---------------- layer-1 SpMM (both views): weighted gather from Y ----------------
// grid = 2N blocks of 96 threads; block b handles view (b>=N), node (b mod N)
__global__ void k_spmm_l1(const float* __restrict__ b1, const float* __restrict__ a1) {
    int bid = blockIdx.x;
    int view = (bid >= N_NODES);
    int node = bid - view * N_NODES;
    const int* __restrict__ ci = view ? d_col2 : d_col;
    int j = threadIdx.x;
    int s = d_row_ptr[node], e = d_row_ptr[node + 1];
    float acc = 0.f;
    int i = s;
    for (; i + 4 <= e; i += 4) {
        int c0 = ci[i],     c1 = ci[i + 1];
        int c2 = ci[i + 2], c3 = ci[i + 3];
        float w0 = d_colw[i],     w1 = d_colw[i + 1];
        float w2 = d_colw[i + 2], w3 = d_colw[i + 3];
        acc += w0 * d_Y[c0 * H + j] + w1 * d_Y[c1 * H + j]
             + w2 * d_Y[c2 * H + j] + w3 * d_Y[c3 * H + j];
    }
    for (; i < e; i++) acc += d_colw[i] * d_Y[ci[i] * H + j];
    float v = acc * d_norm_in[node] + b1[j];
    d_t2[bid * H + j] = (v >= 0.f) ? v : a1[j] * v;
}

// ---------------- layer-2 SpMM (both views): unweighted gather from h2 ----------------
__global__ void k_spmm_l2(const float* __restrict__ b2, const float* __restrict__ a2) {
    int bid = blockIdx.x;
    int view = (bid >= N_NODES);
    int node = bid - view * N_NODES;
    int base = view * N_NODES;
    int j = threadIdx.x;
    int s = d_row_ptr[node], e = d_row_ptr[node + 1];
    float acc = 0.f;
    int i = s;
    for (; i + 4 <= e; i += 4) {
        int c0 = d_col[i] + base,     c1 = d_col[i + 1] + base;
        int c2 = d_col[i + 2] + base, c3 = d_col[i + 3] + base;
        float v0 = d_h2[c0 * H + j];
        float v1 = d_h2[c1 * H + j];
        float v2 = d_h2[c2 * H + j];
        float v3 = d_h2[c3 * H + j];
        acc += (v0 + v1) + (v2 + v3);
    }
    for (; i < e; i++) acc += d_h2[(d_col[i] + base) * H + j];
    float v = acc * d_norm_in[node] + b2[j];
    d_t2[bid * H + j] = (v >= 0.f) ? v : a2[j] * v;
}

// ---------------- output: out[i] = t2[i,:] . wvec + bsum, i in [0,2N) ----------------
__global__ void k_out(float* __restrict__ out) {
    int gw = (blockIdx.x * blockDim.x + threadIdx.x) >> 5;
    int lane = threadIdx.x & 31;
    if (gw >= 2 * N_NODES) return;
    const float* row = d_t2 + gw * H;
    float s = row[lane] * d_wvec[lane]
            + row[lane + 32] * d_wvec[lane + 32]
            + row[lane + 64] * d_wvec[lane + 64];
    #pragma unroll
    for (int off = 16; off > 0; off >>= 1)
        s += __shfl_xor_sync(0xffffffffu, s, off);
    if (lane == 0) out[gw] = s + d_bsum;
}

// ---------------- launch ----------------
extern "C" void kernel_launch(void* const* d_in, const int* in_sizes, int n_in,
                              void* d_out, int out_size) {
    const float* x    = (const float*)d_in[0];
    const int*   src  = (const int*)d_in[1];
    const int*   dst  = (const int*)d_in[2];
    const int*   perm = (const int*)d_in[3];
    const float* W1   = (const float*)d_in[4];
    const float* b1   = (const float*)d_in[5];
    const float* a1   = (const float*)d_in[6];
    const float* W2   = (const float*)d_in[7];
    const float* b2   = (const float*)d_in[8];
    const float* a2   = (const float*)d_in[9];
    const float* Wm   = (const float*)d_in[10];
    const float* bm   = (const float*)d_in[11];
    float* out = (float*)d_out;

    float *hY, *hT2, *hH2, *hNormOut2;
    cudaGetSymbolAddress((void**)&hY, d_Y);
    cudaGetSymbolAddress((void**)&hT2, d_t2);
    cudaGetSymbolAddress((void**)&hH2, d_h2);
    cudaGetSymbolAddress((void**)&hNormOut2, d_norm_out2);

    const int TB = 256;
    // graph structure
    k_zero_deg<<<(N_NODES + TB - 1) / TB, TB>>>();
    k_count<<<(N_EDGES + TB - 1) / TB, TB>>>(src, dst);
    k_norm<<<(N_NODES + TB - 1) / TB, TB>>>();
    k_scan1<<<NCHUNK, 1024>>>();
    k_scan2<<<1, 64>>>();
    k_scan3<<<(N_NODES + TB - 1) / TB, TB>>>();
    k_build_csr<<<(N_EDGES + TB - 1) / TB, TB>>>(src, dst, perm);
    k_fold<<<1, 128>>>(Wm, bm);

    // shared first-layer GEMM: Y = x @ W1 (norm_out folded into edge weights)
    sgemm_n96<<<(N_NODES + 63) / 64, 256>>>(x, F_IN, W1, nullptr, hY, N_NODES);

    // layer 1 for BOTH views: weighted gather + norm_in + bias + PReLU -> t2 [2N,H]
    k_spmm_l1<<<2 * N_NODES, H>>>(b1, a1);

    // layer 2 GEMM over both views at once: h2 = (t2 * norm_out2) @ W2
    sgemm_n96<<<(2 * N_NODES + 63) / 64, 256>>>(hT2, H, W2, hNormOut2, hH2, 2 * N_NODES);

    // layer 2 aggregate for both views -> t2
    k_spmm_l2<<<2 * N_NODES, H>>>(b2, a2);

    // projected row-sum for both views
    k_out<<<(2 * N_NODES * 32 + TB - 1) / TB, TB>>>(out);
}